// round 8
// baseline (speedup 1.0000x reference)
#include <cuda_runtime.h>
#include <cuda_bf16.h>
#include <cuda_pipeline.h>
#include <mma.h>
#include <cstdint>

using namespace nvcuda;

#define NAG  8192
#define OBSD 64
#define HID  128
#define ACTD 16
#define KSPL 2
#define NCH2 (NAG / 64 / KSPL)      // 64 chunks per K2 CTA

// Scratch (device globals: no allocations allowed)
__device__ float          g_h   [NAG * HID];        // fp32 encoder output
__device__ __nv_bfloat16  g_hb  [NAG * HID];        // bf16 h (row-major)
__device__ int            g_q4  [(NAG / 4) * HID];  // packed s8 h: word[kg][col]
__device__ float          g_msgp[KSPL][NAG * HID];  // partial float sums of adj@h
__device__ int            g_degp[KSPL][NAG];        // partial degrees

// ---------------------------------------------------------------------------
// K1: h = tanh(obs @ W1 + b1) -> g_h + g_hb + g_q4.
// 1024 CTAs x 256 threads; one warp per agent.
// ---------------------------------------------------------------------------
__global__ void __launch_bounds__(256) k1_encoder(const float* __restrict__ obs,
                                                  const float* __restrict__ W1,
                                                  const float* __restrict__ b1) {
    __shared__ __align__(16) float sW1[OBSD * HID];   // 32 KB
    __shared__ float sObs[8][OBSD];
    __shared__ unsigned char sQ[8][HID];
    const int t  = threadIdx.x;
    const int a0 = blockIdx.x * 8;

    #pragma unroll
    for (int i = 0; i < (OBSD * HID) / 256; ++i)
        sW1[i * 256 + t] = W1[i * 256 + t];
    #pragma unroll
    for (int i = 0; i < 2; ++i) {
        int idx = i * 256 + t;
        sObs[idx >> 6][idx & 63] = obs[(size_t)(a0 + (idx >> 6)) * OBSD + (idx & 63)];
    }
    __syncthreads();

    const int w = t >> 5, l = t & 31;
    const int agent = a0 + w;
    float acc0 = 0.f, acc1 = 0.f, acc2 = 0.f, acc3 = 0.f;
    #pragma unroll 8
    for (int k = 0; k < OBSD; ++k) {
        float o = sObs[w][k];
        float4 wv = *reinterpret_cast<const float4*>(&sW1[k * HID + l * 4]);
        acc0 = fmaf(o, wv.x, acc0);
        acc1 = fmaf(o, wv.y, acc1);
        acc2 = fmaf(o, wv.z, acc2);
        acc3 = fmaf(o, wv.w, acc3);
    }
    float4 bb = *reinterpret_cast<const float4*>(&b1[l * 4]);
    float h0 = tanhf(acc0 + bb.x);
    float h1 = tanhf(acc1 + bb.y);
    float h2 = tanhf(acc2 + bb.z);
    float h3 = tanhf(acc3 + bb.w);

    const size_t off = (size_t)agent * HID + l * 4;
    float4 hv; hv.x = h0; hv.y = h1; hv.z = h2; hv.w = h3;
    *reinterpret_cast<float4*>(&g_h[off]) = hv;
    __nv_bfloat162 p0 = __floats2bfloat162_rn(h0, h1);
    __nv_bfloat162 p1 = __floats2bfloat162_rn(h2, h3);
    *reinterpret_cast<__nv_bfloat162*>(&g_hb[off])     = p0;
    *reinterpret_cast<__nv_bfloat162*>(&g_hb[off + 2]) = p1;

    sQ[w][l * 4 + 0] = (unsigned char)(__float2int_rn(h0 * 127.f) & 0xFF);
    sQ[w][l * 4 + 1] = (unsigned char)(__float2int_rn(h1 * 127.f) & 0xFF);
    sQ[w][l * 4 + 2] = (unsigned char)(__float2int_rn(h2 * 127.f) & 0xFF);
    sQ[w][l * 4 + 3] = (unsigned char)(__float2int_rn(h3 * 127.f) & 0xFF);
    __syncthreads();

    const int g   = t >> 7;          // 0..1
    const int col = t & 127;
    unsigned wd = (unsigned)sQ[g * 4 + 0][col]
                | ((unsigned)sQ[g * 4 + 1][col] << 8)
                | ((unsigned)sQ[g * 4 + 2][col] << 16)
                | ((unsigned)sQ[g * 4 + 3][col] << 24);
    g_q4[((a0 >> 2) + g) * HID + col] = (int)wd;
}

// ---------------------------------------------------------------------------
// K2 hybrid: rows 0-63 via bf16 WMMA (tensor pipe), rows 64-127 via dp4a (fma
// pipe), same CTA, same chunk stream. Grid 128 = 64 M-tiles x 2 K-halves.
// cp.async ring of 3 stages; one __syncthreads per chunk.
// Stage: A raw int32 [128][272B] | B bf16 [64][272B] | B s8 [16][512B].
// ---------------------------------------------------------------------------
__device__ __forceinline__ unsigned pack2i(int a, int b) {
    return (a ? 0x3F80u : 0u) | (b ? 0x3F800000u : 0u);   // two bf16 {0,1}
}

#define K2_ARAW  34816
#define K2_BBF   17408
#define K2_BS8   8192
#define K2_STAGE (K2_ARAW + K2_BBF + K2_BS8)        // 60416
#define K2_RING  (3 * K2_STAGE)                     // 181248
#define K2_ABF   9216                               // bf16 [64][72]
#define K2_A4    5120                               // int [64][20]
#define K2_SMEM  (K2_RING + 2 * K2_ABF + 2 * K2_A4) // 209920

__global__ void __launch_bounds__(512, 1) k2_msg(const int* __restrict__ adj) {
    extern __shared__ __align__(16) char sm2[];
    __shared__ int sDeg[128];

    const int t    = threadIdx.x;
    const int wid  = t >> 5;
    const int mt   = blockIdx.x & 63;
    const int half = blockIdx.x >> 6;          // 0..1
    const int m0   = mt * 128;
    const int k0   = half * (NAG / KSPL);      // 4096
    const int kg0  = half * (NAG / KSPL / 4);  // 1024
    if (t < 128) sDeg[t] = 0;

    // staging maps
    const int irow = t >> 2;                   // 0..127 (A raw)
    const int ig   = t & 3;
    const char* gA   = reinterpret_cast<const char*>(adj) +
                       (size_t)(m0 + irow) * (NAG * 4) + (size_t)k0 * 4 + ig * 64;
    const int  krow  = t >> 3;                 // 0..63 (B bf16)
    const int  kseg  = t & 7;
    const char* gBbf = reinterpret_cast<const char*>(g_hb) +
                       (size_t)(k0 + krow) * (HID * 2) + kseg * 32;
    const int  bkg   = t >> 5;                 // 0..15 (B s8)
    const int  bseg  = t & 31;
    const char* gBs8 = reinterpret_cast<const char*>(g_q4) +
                       (size_t)(kg0 + bkg) * (HID * 4) + bseg * 16;

    // dp4a compute map (warps 8-15): local rows 4*trow2.., cols 8*tcol..
    const int lt    = t - 256;
    const int trow2 = lt >> 4;                 // 0..15 (valid when t>=256)
    const int tcol  = t & 15;

    // WMMA compute map (warps 0-7): 2 wm x 4 wn grid of 32x32 tiles, all 4 ks
    const int wm = wid & 1;
    const int wn = wid >> 1;                   // 0..3

    wmma::fragment<wmma::accumulator, 16, 16, 16, float> wacc[2][2];
    int iacc[4][8];
    if (wid < 8) {
        #pragma unroll
        for (int i = 0; i < 2; ++i)
            #pragma unroll
            for (int j = 0; j < 2; ++j)
                wmma::fill_fragment(wacc[i][j], 0.0f);
    } else {
        #pragma unroll
        for (int r = 0; r < 4; ++r)
            #pragma unroll
            for (int j = 0; j < 8; ++j) iacc[r][j] = 0;
    }

    auto issue_stage = [&](int c) {
        char* st = sm2 + (c % 3) * K2_STAGE;
        char* sA = st;
        char* sB = st + K2_ARAW;
        char* sQ8 = st + K2_ARAW + K2_BBF;
        const char* ga = gA + (size_t)c * 256;
        const char* gb = gBbf + (size_t)c * 64 * (HID * 2);
        const char* gq = gBs8 + (size_t)c * 16 * (HID * 4);
        #pragma unroll
        for (int q = 0; q < 4; ++q)
            __pipeline_memcpy_async(sA + irow * 272 + ig * 64 + q * 16, ga + q * 16, 16);
        #pragma unroll
        for (int q = 0; q < 2; ++q)
            __pipeline_memcpy_async(sB + krow * 272 + kseg * 32 + q * 16, gb + q * 16, 16);
        __pipeline_memcpy_async(sQ8 + bkg * 512 + bseg * 16, gq, 16);
    };

    issue_stage(0); __pipeline_commit();
    issue_stage(1); __pipeline_commit();

    int cnt = 0;
    for (int c = 0; c < NCH2; ++c) {
        char* st    = sm2 + (c % 3) * K2_STAGE;
        char* sAraw = st;
        char* sAbf  = sm2 + K2_RING + (c & 1) * K2_ABF;
        char* sA4   = sm2 + K2_RING + 2 * K2_ABF + (c & 1) * K2_A4;

        __pipeline_wait_prior(1);      // stage c landed (this thread's copies)

        // convert own 16 raw int32 of A
        {
            const int4* src = reinterpret_cast<const int4*>(sAraw + irow * 272 + ig * 64);
            int4 v0 = src[0], v1 = src[1], v2 = src[2], v3 = src[3];
            cnt += v0.x + v0.y + v0.z + v0.w + v1.x + v1.y + v1.z + v1.w +
                   v2.x + v2.y + v2.z + v2.w + v3.x + v3.y + v3.z + v3.w;
            if (t < 256) {             // rows 0-63 -> bf16 for WMMA
                uint4 w0, w1;
                w0.x = pack2i(v0.x, v0.y); w0.y = pack2i(v0.z, v0.w);
                w0.z = pack2i(v1.x, v1.y); w0.w = pack2i(v1.z, v1.w);
                w1.x = pack2i(v2.x, v2.y); w1.y = pack2i(v2.z, v2.w);
                w1.z = pack2i(v3.x, v3.y); w1.w = pack2i(v3.z, v3.w);
                uint4* dst = reinterpret_cast<uint4*>(sAbf + irow * 144 + ig * 32);
                dst[0] = w0; dst[1] = w1;
            } else {                   // rows 64-127 -> packed bytes for dp4a
                int4 w;
                w.x = v0.x | (v0.y << 8) | (v0.z << 16) | (v0.w << 24);
                w.y = v1.x | (v1.y << 8) | (v1.z << 16) | (v1.w << 24);
                w.z = v2.x | (v2.y << 8) | (v2.z << 16) | (v2.w << 24);
                w.w = v3.x | (v3.y << 8) | (v3.z << 16) | (v3.w << 24);
                *reinterpret_cast<int4*>(sA4 + (irow - 64) * 80 + ig * 16) = w;
            }
        }
        __syncthreads();               // converted A + B visible; prev compute done

        if (c + 2 < NCH2) issue_stage(c + 2);
        __pipeline_commit();

        if (wid < 8) {
            // WMMA: rows wm*32..+31, cols wn*32..+31, all 4 ks
            const __nv_bfloat16* A = reinterpret_cast<const __nv_bfloat16*>(sAbf);
            const __nv_bfloat16* B = reinterpret_cast<const __nv_bfloat16*>(st + K2_ARAW);
            #pragma unroll
            for (int ks = 0; ks < 4; ++ks) {
                wmma::fragment<wmma::matrix_a, 16, 16, 16, __nv_bfloat16, wmma::row_major> af[2];
                wmma::fragment<wmma::matrix_b, 16, 16, 16, __nv_bfloat16, wmma::row_major> bf[2];
                #pragma unroll
                for (int i = 0; i < 2; ++i)
                    wmma::load_matrix_sync(af[i], &A[(wm * 32 + i * 16) * 72 + ks * 16], 72);
                #pragma unroll
                for (int j = 0; j < 2; ++j)
                    wmma::load_matrix_sync(bf[j], &B[(ks * 16) * 136 + wn * 32 + j * 16], 136);
                #pragma unroll
                for (int i = 0; i < 2; ++i)
                    #pragma unroll
                    for (int j = 0; j < 2; ++j)
                        wmma::mma_sync(wacc[i][j], af[i], bf[j], wacc[i][j]);
            }
        } else {
            // dp4a: rows 64 + 4*trow2 .., cols tcol*8..
            const int* A4 = reinterpret_cast<const int*>(sA4);
            const int* B4 = reinterpret_cast<const int*>(st + K2_ARAW + K2_BBF);
            #pragma unroll 4
            for (int kg = 0; kg < 16; ++kg) {
                int a[4];
                #pragma unroll
                for (int r = 0; r < 4; ++r)
                    a[r] = A4[(4 * trow2 + r) * 20 + kg];
                int4 b0 = *reinterpret_cast<const int4*>(&B4[kg * 128 + tcol * 8]);
                int4 b1 = *reinterpret_cast<const int4*>(&B4[kg * 128 + tcol * 8 + 4]);
                #pragma unroll
                for (int r = 0; r < 4; ++r) {
                    iacc[r][0] = __dp4a(a[r], b0.x, iacc[r][0]);
                    iacc[r][1] = __dp4a(a[r], b0.y, iacc[r][1]);
                    iacc[r][2] = __dp4a(a[r], b0.z, iacc[r][2]);
                    iacc[r][3] = __dp4a(a[r], b0.w, iacc[r][3]);
                    iacc[r][4] = __dp4a(a[r], b1.x, iacc[r][4]);
                    iacc[r][5] = __dp4a(a[r], b1.y, iacc[r][5]);
                    iacc[r][6] = __dp4a(a[r], b1.z, iacc[r][6]);
                    iacc[r][7] = __dp4a(a[r], b1.w, iacc[r][7]);
                }
            }
        }
    }

    atomicAdd(&sDeg[irow], cnt);
    __syncthreads();                   // all compute done; ring memory reusable

    float* dst = g_msgp[half];
    if (wid < 8) {
        // WMMA rows 0-63: via smem fp32 tile [64][132]
        float* sAcc = reinterpret_cast<float*>(sm2);
        #pragma unroll
        for (int i = 0; i < 2; ++i)
            #pragma unroll
            for (int j = 0; j < 2; ++j)
                wmma::store_matrix_sync(&sAcc[(wm * 32 + i * 16) * 132 + wn * 32 + j * 16],
                                        wacc[i][j], 132, wmma::mem_row_major);
    } else {
        // dp4a rows 64-127: straight from registers, scale 1/127
        const float s = 1.0f / 127.0f;
        #pragma unroll
        for (int r = 0; r < 4; ++r) {
            float* p = dst + (size_t)(m0 + 64 + 4 * trow2 + r) * HID + tcol * 8;
            float4 f0, f1;
            f0.x = iacc[r][0] * s; f0.y = iacc[r][1] * s;
            f0.z = iacc[r][2] * s; f0.w = iacc[r][3] * s;
            f1.x = iacc[r][4] * s; f1.y = iacc[r][5] * s;
            f1.z = iacc[r][6] * s; f1.w = iacc[r][7] * s;
            *reinterpret_cast<float4*>(p)     = f0;
            *reinterpret_cast<float4*>(p + 4) = f1;
        }
    }
    __syncthreads();

    {   // WMMA tile -> gmem (8192 floats, all 512 threads)
        const float* sAcc = reinterpret_cast<const float*>(sm2);
        #pragma unroll
        for (int i = 0; i < 16; ++i) {
            int idx = i * 512 + t;
            int row = idx >> 7, col = idx & 127;
            dst[(size_t)(m0 + row) * HID + col] = sAcc[row * 132 + col];
        }
    }
    if (t < 128) g_degp[half][m0 + t] = sDeg[t];
}

// ---------------------------------------------------------------------------
// K3: merge partials -> msg; hid = tanh([h,msg] @ W2 + b2); out = hid @ W3 + b3.
// ---------------------------------------------------------------------------
#define K3_SMEM (4 * (32768 + 16448 + 2048 + 128 + 16 + 64))   // 205,888 B

__global__ void __launch_bounds__(256, 1) k3_actor(float* __restrict__ out,
        const float* __restrict__ W2, const float* __restrict__ b2,
        const float* __restrict__ W3, const float* __restrict__ b3) {
    extern __shared__ __align__(16) float sm[];
    float* sW2 = sm;                   // [256][128]
    float* sC  = sm + 32768;           // [64][257]; reused as hid [64][129]
    float* sW3 = sC + 16448;           // [128][16]
    float* sb2 = sW3 + 2048;
    float* sb3 = sb2 + 128;
    float* sInv = sb3 + 16;            // [64]

    const int t  = threadIdx.x;
    const int a0 = blockIdx.x * 64;

    #pragma unroll 4
    for (int i = 0; i < 128; ++i) sW2[i * 256 + t] = W2[i * 256 + t];
    #pragma unroll
    for (int i = 0; i < 8; ++i)   sW3[i * 256 + t] = W3[i * 256 + t];
    if (t < 128) sb2[t] = b2[t];
    if (t < 16)  sb3[t] = b3[t];
    if (t < 64) {
        int d = 0;
        #pragma unroll
        for (int p = 0; p < KSPL; ++p) d += g_degp[p][a0 + t];
        sInv[t] = 1.0f / (float)max(d, 1);
    }
    __syncthreads();
    #pragma unroll 4
    for (int i = 0; i < 32; ++i) {
        int idx = i * 256 + t;
        int a = idx >> 7, k = idx & 127;
        sC[a * 257 + k] = g_h[(size_t)(a0 + a) * HID + k];
        float s = 0.f;
        #pragma unroll
        for (int p = 0; p < KSPL; ++p) s += g_msgp[p][(size_t)(a0 + a) * HID + k];
        sC[a * 257 + 128 + k] = s * sInv[a];
    }
    __syncthreads();

    const int ar = t >> 4;
    const int cc = t & 15;
    float acc[4][8];
    #pragma unroll
    for (int j = 0; j < 4; ++j)
        #pragma unroll
        for (int i = 0; i < 8; ++i) acc[j][i] = 0.f;

    #pragma unroll 2
    for (int k = 0; k < 2 * HID; ++k) {
        float4 w0 = *reinterpret_cast<const float4*>(&sW2[k * 128 + cc * 8]);
        float4 w1 = *reinterpret_cast<const float4*>(&sW2[k * 128 + cc * 8 + 4]);
        #pragma unroll
        for (int j = 0; j < 4; ++j) {
            float cv = sC[(ar * 4 + j) * 257 + k];
            acc[j][0] = fmaf(cv, w0.x, acc[j][0]);
            acc[j][1] = fmaf(cv, w0.y, acc[j][1]);
            acc[j][2] = fmaf(cv, w0.z, acc[j][2]);
            acc[j][3] = fmaf(cv, w0.w, acc[j][3]);
            acc[j][4] = fmaf(cv, w1.x, acc[j][4]);
            acc[j][5] = fmaf(cv, w1.y, acc[j][5]);
            acc[j][6] = fmaf(cv, w1.z, acc[j][6]);
            acc[j][7] = fmaf(cv, w1.w, acc[j][7]);
        }
    }
    __syncthreads();
    float* sH = sC;                       // [64][129]
    #pragma unroll
    for (int j = 0; j < 4; ++j) {
        int a = ar * 4 + j;
        #pragma unroll
        for (int i = 0; i < 8; ++i) {
            int ccol = cc * 8 + i;
            sH[a * 129 + ccol] = tanhf(acc[j][i] + sb2[ccol]);
        }
    }
    __syncthreads();

    const int a  = t >> 2;
    const int cq = t & 3;
    float4 lg; lg.x = 0.f; lg.y = 0.f; lg.z = 0.f; lg.w = 0.f;
    #pragma unroll 8
    for (int k = 0; k < HID; ++k) {
        float hv  = sH[a * 129 + k];
        float4 w3 = *reinterpret_cast<const float4*>(&sW3[k * 16 + cq * 4]);
        lg.x = fmaf(hv, w3.x, lg.x);
        lg.y = fmaf(hv, w3.y, lg.y);
        lg.z = fmaf(hv, w3.z, lg.z);
        lg.w = fmaf(hv, w3.w, lg.w);
    }
    lg.x += sb3[cq * 4 + 0];
    lg.y += sb3[cq * 4 + 1];
    lg.z += sb3[cq * 4 + 2];
    lg.w += sb3[cq * 4 + 3];
    *reinterpret_cast<float4*>(&out[(size_t)(a0 + a) * ACTD + cq * 4]) = lg;
}

// ---------------------------------------------------------------------------
extern "C" void kernel_launch(void* const* d_in, const int* in_sizes, int n_in,
                              void* d_out, int out_size) {
    const float* obs = (const float*)d_in[0];
    const int*   adj = (const int*)  d_in[1];
    const float* W1  = (const float*)d_in[2];
    const float* b1  = (const float*)d_in[3];
    const float* W2  = (const float*)d_in[4];
    const float* b2  = (const float*)d_in[5];
    const float* W3  = (const float*)d_in[6];
    const float* b3  = (const float*)d_in[7];
    float* out = (float*)d_out;

    cudaFuncSetAttribute(k2_msg,   cudaFuncAttributeMaxDynamicSharedMemorySize, K2_SMEM);
    cudaFuncSetAttribute(k3_actor, cudaFuncAttributeMaxDynamicSharedMemorySize, K3_SMEM);

    k1_encoder<<<NAG / 8, 256>>>(obs, W1, b1);
    k2_msg    <<<64 * KSPL, 512, K2_SMEM>>>(adj);
    k3_actor  <<<NAG / 64, 256, K3_SMEM>>>(out, W2, b2, W3, b3);
}